// round 5
// baseline (speedup 1.0000x reference)
#include <cuda_runtime.h>
#include <math.h>

#define NROWS 1048576
#define D     128
#define G     4096
#define HID   50
#define GDIM  201
#define TAILW 33
#define OUTW  (GDIM + TAILW)   // 234

#define THREADS     256
#define RPS         32                    // rows per stage
#define STAGES      4
#define ROW_BYTES   512                   // 128 floats
#define STAGE_BYTES (RPS * ROW_BYTES)     // 16 KB
#define RING_BYTES  (STAGES * STAGE_BYTES) // 64 KB dynamic smem

// ---------------- persistent scratch (no allocations allowed) ----------------
__device__ int g_start[G + 1];

// ---------------- kernel 0: group boundaries via parallel lower_bound --------
__global__ void bounds_kernel(const int* __restrict__ batch) {
    int g = blockIdx.x * blockDim.x + threadIdx.x;
    if (g > G) return;
    int lo = 0, hi = NROWS;
    while (lo < hi) {
        int mid = (lo + hi) >> 1;
        if (__ldg(&batch[mid]) < g) lo = mid + 1; else hi = mid;
    }
    g_start[g] = lo;   // first row with batch >= g ; g_start[G] = NROWS
}

// ---------------- cp.async stage producer ----------------
__device__ __forceinline__ void issue_stage(const char* __restrict__ xbase,
                                            int stage_idx, int rows,
                                            char* slot, int t, bool active) {
    if (active) {
        int rbase = stage_idx * RPS;
#pragma unroll
        for (int j = 0; j < (STAGE_BYTES / 16) / THREADS; ++j) {   // 4 chunks/thread
            int ci  = t + j * THREADS;
            int rr  = ci >> 5;            // 32 x 16B chunks per row
            int off = (ci & 31) << 4;
            int row = rbase + rr;
            if (row < rows) {
                unsigned daddr = (unsigned)__cvta_generic_to_shared(slot + rr * ROW_BYTES + off);
                const char* src = xbase + (size_t)row * ROW_BYTES + off;
                asm volatile("cp.async.cg.shared.global [%0], [%1], 16;"
                             :: "r"(daddr), "l"(src) : "memory");
            }
        }
    }
    asm volatile("cp.async.commit_group;" ::: "memory");
}

// ---------------- fused kernel: stream group -> aggr -> MLP -> out ----------
extern __shared__ char ring[];

__global__ void __launch_bounds__(THREADS)
fused_kernel(const float* __restrict__ x, const float* __restrict__ u,
             const float* __restrict__ W1, const float* __restrict__ b1,
             const float* __restrict__ ln_g, const float* __restrict__ ln_b,
             const float* __restrict__ W2, const float* __restrict__ b2,
             float* __restrict__ out) {
    __shared__ float red[4][8][D];     // 16 KB warp partials: sum,sum2,max,min
    __shared__ float aggr[4 * D];
    __shared__ float part[HID][4];
    __shared__ float hn[HID];
    __shared__ float mu_s, rstd_s;

    const int gid  = blockIdx.x;
    const int t    = threadIdx.x;
    const int w    = t >> 5;
    const int lane = t & 31;

    const int s    = g_start[gid];
    const int e    = g_start[gid + 1];
    const int rows = e - s;
    const char* xbase = (const char*)x + (size_t)s * ROW_BYTES;

    const float NEGI = __int_as_float(0xff800000);
    const float POSI = __int_as_float(0x7f800000);
    float4 as  = make_float4(0.f, 0.f, 0.f, 0.f);
    float4 as2 = make_float4(0.f, 0.f, 0.f, 0.f);
    float4 amx = make_float4(NEGI, NEGI, NEGI, NEGI);
    float4 amn = make_float4(POSI, POSI, POSI, POSI);

    const int nst = (rows + RPS - 1) / RPS;

    // prologue: fill pipeline
#pragma unroll
    for (int k = 0; k < STAGES; ++k)
        issue_stage(xbase, k, rows, ring + k * STAGE_BYTES, t, k < nst);

    for (int i = 0; i < nst; ++i) {
        asm volatile("cp.async.wait_group %0;" :: "n"(STAGES - 1) : "memory");
        __syncthreads();

        const char* slot = ring + (i % STAGES) * STAGE_BYTES;
        const int rbase = i * RPS;
#pragma unroll
        for (int k = 0; k < RPS / 8; ++k) {       // 4 rows per warp per stage
            int rr  = w * (RPS / 8) + k;
            int row = rbase + rr;
            if (row < rows) {
                float4 v = *(const float4*)(slot + rr * ROW_BYTES + lane * 16);
                as.x += v.x; as.y += v.y; as.z += v.z; as.w += v.w;
                as2.x = fmaf(v.x, v.x, as2.x);
                as2.y = fmaf(v.y, v.y, as2.y);
                as2.z = fmaf(v.z, v.z, as2.z);
                as2.w = fmaf(v.w, v.w, as2.w);
                amx.x = fmaxf(amx.x, v.x); amx.y = fmaxf(amx.y, v.y);
                amx.z = fmaxf(amx.z, v.z); amx.w = fmaxf(amx.w, v.w);
                amn.x = fminf(amn.x, v.x); amn.y = fminf(amn.y, v.y);
                amn.z = fminf(amn.z, v.z); amn.w = fminf(amn.w, v.w);
            }
        }
        __syncthreads();
        issue_stage(xbase, i + STAGES, rows,
                    ring + (i % STAGES) * STAGE_BYTES, t, i + STAGES < nst);
    }

    // ---- cross-warp reduction ----
    *(float4*)&red[0][w][lane * 4] = as;
    *(float4*)&red[1][w][lane * 4] = as2;
    *(float4*)&red[2][w][lane * 4] = amx;
    *(float4*)&red[3][w][lane * 4] = amn;
    __syncthreads();

    if (t < D) {
        float sm = 0.f, sm2 = 0.f, mx = NEGI, mn = POSI;
#pragma unroll
        for (int ww = 0; ww < 8; ++ww) {
            sm  += red[0][ww][t];
            sm2 += red[1][ww][t];
            mx   = fmaxf(mx, red[2][ww][t]);
            mn   = fminf(mn, red[3][ww][t]);
        }
        float c    = fmaxf((float)rows, 1.0f);
        float mean = sm / c;
        float var  = sm2 / c - mean * mean;
        aggr[t]         = mean;
        aggr[D + t]     = sqrtf(fmaxf(var, 0.0f) + 1e-5f);
        aggr[2 * D + t] = mx;
        aggr[3 * D + t] = mn;
    }
    __syncthreads();

    // ---- h = aggr(512) @ W1(512,50): 4 slice-partials per output ----
    if (t < 4 * HID) {
        int j  = t >> 2;
        int sl = t & 3;
        const float* __restrict__ wp = W1 + (sl * D) * HID + j;
        const float* __restrict__ a  = aggr + sl * D;
        float acc = 0.0f;
#pragma unroll 8
        for (int k = 0; k < D; ++k) acc = fmaf(a[k], wp[k * HID], acc);
        part[j][sl] = acc;
    }
    __syncthreads();

    if (t < HID) {
        float hv = part[t][0] + part[t][1] + part[t][2] + part[t][3] + b1[t];
        const float SC = 1.0507009873554804934193349852946f;
        const float AL = 1.6732632423543772848170429916717f;
        hv = (hv > 0.0f) ? SC * hv : SC * AL * expm1f(hv);
        hn[t] = hv;
    }
    __syncthreads();

    if (t == 0) {
        float m = 0.0f;
#pragma unroll
        for (int k = 0; k < HID; ++k) m += hn[k];
        m /= (float)HID;
        float v = 0.0f;
#pragma unroll
        for (int k = 0; k < HID; ++k) { float d = hn[k] - m; v = fmaf(d, d, v); }
        v /= (float)HID;
        mu_s   = m;
        rstd_s = rsqrtf(v + 1e-5f);
    }
    __syncthreads();

    if (t < HID) hn[t] = (hn[t] - mu_s) * rstd_s * ln_g[t] + ln_b[t];
    __syncthreads();

    if (t < GDIM) {
        float acc = b2[t];
#pragma unroll
        for (int k = 0; k < HID; ++k) acc = fmaf(hn[k], W2[k * GDIM + t], acc);
        out[gid * OUTW + t] = acc;
    } else if (t < OUTW) {
        out[gid * OUTW + t] = u[gid * 64 + 31 + (t - GDIM)];
    }
}

// ---------------- launch ----------------
extern "C" void kernel_launch(void* const* d_in, const int* in_sizes, int n_in,
                              void* d_out, int out_size) {
    const float* x     = (const float*)d_in[0];
    // d_in[1] edge_index, d_in[2] edge_attr: unused by the reference
    const float* u     = (const float*)d_in[3];
    const int*   batch = (const int*)d_in[4];
    const float* W1    = (const float*)d_in[5];
    const float* b1    = (const float*)d_in[6];
    const float* ln_g  = (const float*)d_in[7];
    const float* ln_b  = (const float*)d_in[8];
    const float* W2    = (const float*)d_in[9];
    const float* b2    = (const float*)d_in[10];
    float* out = (float*)d_out;

    cudaFuncSetAttribute(fused_kernel,
                         cudaFuncAttributeMaxDynamicSharedMemorySize, RING_BYTES);

    bounds_kernel<<<(G + 1 + 255) / 256, 256>>>(batch);
    fused_kernel<<<G, THREADS, RING_BYTES>>>(x, u, W1, b1, ln_g, ln_b, W2, b2, out);
}

// round 8
// speedup vs baseline: 1.2818x; 1.2818x over previous
#include <cuda_runtime.h>
#include <math.h>

#define NROWS 1048576
#define D     128
#define G     4096
#define HID   50
#define GDIM  201
#define TAILW 33
#define OUTW  (GDIM + TAILW)   // 234

#define THREADS     256
#define RPS         32                       // rows per stage
#define STAGES      4
#define ROW_BYTES   512                      // 128 floats
#define STAGE_BYTES (RPS * ROW_BYTES)        // 16 KB
#define RING_BYTES  (STAGES * STAGE_BYTES)   // 64 KB dynamic smem

// ---------------- persistent scratch (no allocations allowed) ----------------
__device__ int g_start[G + 1];

// ---------------- kernel 0: group boundaries via parallel lower_bound --------
__global__ void bounds_kernel(const int* __restrict__ batch) {
    int g = blockIdx.x * blockDim.x + threadIdx.x;
    if (g > G) return;
    int lo = 0, hi = NROWS;
    while (lo < hi) {
        int mid = (lo + hi) >> 1;
        if (__ldg(&batch[mid]) < g) lo = mid + 1; else hi = mid;
    }
    g_start[g] = lo;   // first row with batch >= g ; g_start[G] = NROWS
}

// ---------------- mbarrier helpers ----------------
__device__ __forceinline__ unsigned smem_u32(const void* p) {
    return (unsigned)__cvta_generic_to_shared(p);
}
__device__ __forceinline__ void mbar_init(unsigned mbar, unsigned count) {
    asm volatile("mbarrier.init.shared.b64 [%0], %1;" :: "r"(mbar), "r"(count) : "memory");
}
__device__ __forceinline__ void mbar_expect_tx(unsigned mbar, unsigned bytes) {
    asm volatile("mbarrier.arrive.expect_tx.shared.b64 _, [%0], %1;"
                 :: "r"(mbar), "r"(bytes) : "memory");
}
__device__ __forceinline__ void mbar_wait(unsigned mbar, unsigned parity) {
    asm volatile(
        "{\n\t"
        ".reg .pred P;\n\t"
        "WAIT_%=:\n\t"
        "mbarrier.try_wait.parity.acquire.cta.shared::cta.b64 P, [%0], %1, 0x989680;\n\t"
        "@P bra.uni DONE_%=;\n\t"
        "bra.uni WAIT_%=;\n\t"
        "DONE_%=:\n\t"
        "}"
        :: "r"(mbar), "r"(parity) : "memory");
}
__device__ __forceinline__ void bulk_copy_g2s(unsigned dst_smem, const void* src,
                                              unsigned bytes, unsigned mbar) {
    asm volatile(
        "cp.async.bulk.shared::cta.global.mbarrier::complete_tx::bytes [%0], [%1], %2, [%3];"
        :: "r"(dst_smem), "l"(src), "r"(bytes), "r"(mbar) : "memory");
}

// ---------------- fused kernel: TMA-stream group -> aggr -> MLP -> out ------
extern __shared__ char ring[];   // 64 KB; reused as reduction scratch after streaming

__global__ void __launch_bounds__(THREADS)
fused_kernel(const float* __restrict__ x, const float* __restrict__ u,
             const float* __restrict__ W1, const float* __restrict__ b1,
             const float* __restrict__ ln_g, const float* __restrict__ ln_b,
             const float* __restrict__ W2, const float* __restrict__ b2,
             float* __restrict__ out) {
    __shared__ __align__(8) unsigned long long mbar[STAGES];
    __shared__ float aggr[4 * D];
    __shared__ float part[HID][4];
    __shared__ float hn[HID];
    __shared__ float mu_s, rstd_s;

    const int gid  = blockIdx.x;
    const int t    = threadIdx.x;
    const int w    = t >> 5;
    const int lane = t & 31;

    const int s    = g_start[gid];
    const int rows = g_start[gid + 1] - s;
    const char* xbase = (const char*)x + (size_t)s * ROW_BYTES;
    const int nst = (rows + RPS - 1) / RPS;

    if (t == 0) {
#pragma unroll
        for (int k = 0; k < STAGES; ++k) mbar_init(smem_u32(&mbar[k]), 1);
    }
    __syncthreads();

    const float NEGI = __int_as_float(0xff800000);
    const float POSI = __int_as_float(0x7f800000);
    float4 as  = make_float4(0.f, 0.f, 0.f, 0.f);
    float4 as2 = make_float4(0.f, 0.f, 0.f, 0.f);
    float4 amx = make_float4(NEGI, NEGI, NEGI, NEGI);
    float4 amn = make_float4(POSI, POSI, POSI, POSI);

    // prologue: fill pipeline (single bulk copy per stage)
    if (t == 0) {
        for (int k = 0; k < STAGES && k < nst; ++k) {
            unsigned bytes = (unsigned)(min(rows - k * RPS, RPS) * ROW_BYTES);
            unsigned mb = smem_u32(&mbar[k]);
            mbar_expect_tx(mb, bytes);
            bulk_copy_g2s(smem_u32(ring + k * STAGE_BYTES),
                          xbase + (size_t)k * STAGE_BYTES, bytes, mb);
        }
    }

    for (int i = 0; i < nst; ++i) {
        const int slot = i % STAGES;
        mbar_wait(smem_u32(&mbar[slot]), (i / STAGES) & 1);

        const char* sp   = ring + slot * STAGE_BYTES;
        const int rbase  = i * RPS;
#pragma unroll
        for (int k = 0; k < RPS / 8; ++k) {       // 4 rows per warp per stage
            int rr  = w * (RPS / 8) + k;
            if (rbase + rr < rows) {
                float4 v = *(const float4*)(sp + rr * ROW_BYTES + lane * 16);
                as.x += v.x; as.y += v.y; as.z += v.z; as.w += v.w;
                as2.x = fmaf(v.x, v.x, as2.x);
                as2.y = fmaf(v.y, v.y, as2.y);
                as2.z = fmaf(v.z, v.z, as2.z);
                as2.w = fmaf(v.w, v.w, as2.w);
                amx.x = fmaxf(amx.x, v.x); amx.y = fmaxf(amx.y, v.y);
                amx.z = fmaxf(amx.z, v.z); amx.w = fmaxf(amx.w, v.w);
                amn.x = fminf(amn.x, v.x); amn.y = fminf(amn.y, v.y);
                amn.z = fminf(amn.z, v.z); amn.w = fminf(amn.w, v.w);
            }
        }
        __syncthreads();   // slot fully consumed by all warps
        if (t == 0 && i + STAGES < nst) {
            int k = i + STAGES;
            unsigned bytes = (unsigned)(min(rows - k * RPS, RPS) * ROW_BYTES);
            unsigned mb = smem_u32(&mbar[slot]);
            mbar_expect_tx(mb, bytes);
            bulk_copy_g2s(smem_u32(ring + slot * STAGE_BYTES),
                          xbase + (size_t)k * STAGE_BYTES, bytes, mb);
        }
    }
    __syncthreads();

    // ---- cross-warp reduction (reuse ring as scratch: 4*8*128 floats = 16 KB)
    float* red = (float*)ring;     // [pipe][warp][col]
    *(float4*)&red[(0 * 8 + w) * D + lane * 4] = as;
    *(float4*)&red[(1 * 8 + w) * D + lane * 4] = as2;
    *(float4*)&red[(2 * 8 + w) * D + lane * 4] = amx;
    *(float4*)&red[(3 * 8 + w) * D + lane * 4] = amn;
    __syncthreads();

    if (t < D) {
        float sm = 0.f, sm2 = 0.f, mx = NEGI, mn = POSI;
#pragma unroll
        for (int ww = 0; ww < 8; ++ww) {
            sm  += red[(0 * 8 + ww) * D + t];
            sm2 += red[(1 * 8 + ww) * D + t];
            mx   = fmaxf(mx, red[(2 * 8 + ww) * D + t]);
            mn   = fminf(mn, red[(3 * 8 + ww) * D + t]);
        }
        float c    = fmaxf((float)rows, 1.0f);
        float mean = sm / c;
        float var  = sm2 / c - mean * mean;
        aggr[t]         = mean;
        aggr[D + t]     = sqrtf(fmaxf(var, 0.0f) + 1e-5f);
        aggr[2 * D + t] = mx;
        aggr[3 * D + t] = mn;
    }
    __syncthreads();

    // ---- h = aggr(512) @ W1(512,50): 4 slice-partials per output ----
    if (t < 4 * HID) {
        int j  = t >> 2;
        int sl = t & 3;
        const float* __restrict__ wp = W1 + (sl * D) * HID + j;
        const float* __restrict__ a  = aggr + sl * D;
        float acc = 0.0f;
#pragma unroll 8
        for (int k = 0; k < D; ++k) acc = fmaf(a[k], wp[k * HID], acc);
        part[j][sl] = acc;
    }
    __syncthreads();

    if (t < HID) {
        float hv = part[t][0] + part[t][1] + part[t][2] + part[t][3] + b1[t];
        const float SC = 1.0507009873554804934193349852946f;
        const float AL = 1.6732632423543772848170429916717f;
        hv = (hv > 0.0f) ? SC * hv : SC * AL * expm1f(hv);
        hn[t] = hv;
    }
    __syncthreads();

    if (t == 0) {
        float m = 0.0f;
#pragma unroll
        for (int k = 0; k < HID; ++k) m += hn[k];
        m /= (float)HID;
        float v = 0.0f;
#pragma unroll
        for (int k = 0; k < HID; ++k) { float d = hn[k] - m; v = fmaf(d, d, v); }
        v /= (float)HID;
        mu_s   = m;
        rstd_s = rsqrtf(v + 1e-5f);
    }
    __syncthreads();

    if (t < HID) hn[t] = (hn[t] - mu_s) * rstd_s * ln_g[t] + ln_b[t];
    __syncthreads();

    if (t < GDIM) {
        float acc = b2[t];
#pragma unroll
        for (int k = 0; k < HID; ++k) acc = fmaf(hn[k], W2[k * GDIM + t], acc);
        out[gid * OUTW + t] = acc;
    } else if (t < OUTW) {
        out[gid * OUTW + t] = u[gid * 64 + 31 + (t - GDIM)];
    }
}

// ---------------- launch ----------------
extern "C" void kernel_launch(void* const* d_in, const int* in_sizes, int n_in,
                              void* d_out, int out_size) {
    const float* x     = (const float*)d_in[0];
    // d_in[1] edge_index, d_in[2] edge_attr: unused by the reference
    const float* u     = (const float*)d_in[3];
    const int*   batch = (const int*)d_in[4];
    const float* W1    = (const float*)d_in[5];
    const float* b1    = (const float*)d_in[6];
    const float* ln_g  = (const float*)d_in[7];
    const float* ln_b  = (const float*)d_in[8];
    const float* W2    = (const float*)d_in[9];
    const float* b2    = (const float*)d_in[10];
    float* out = (float*)d_out;

    cudaFuncSetAttribute(fused_kernel,
                         cudaFuncAttributeMaxDynamicSharedMemorySize, RING_BYTES);

    bounds_kernel<<<(G + 1 + 255) / 256, 256>>>(batch);
    fused_kernel<<<G, THREADS, RING_BYTES>>>(x, u, W1, b1, ln_g, ln_b, W2, b2, out);
}